// round 15
// baseline (speedup 1.0000x reference)
#include <cuda_runtime.h>
#include <cuda_bf16.h>
#include <math.h>
#include <cstdint>

// ---------------------------------------------------------------- dims
constexpr int B  = 4;
constexpr int L  = 2048;
constexpr int D  = 1024;
constexpr int DH = 2048;
constexpr int M_TOT = B * L;            // 8192

// scan chunking
constexpr int NC = 32;
constexpr int CL = L / NC;              // 64

// ---------------------------------------------------------------- scratch
// Referenced ONLY from device code (host-side symbol addresses are invalid).
__device__ __align__(16) float          g_h  [(size_t)M_TOT * DH];
__device__ __align__(16) __nv_bfloat16  g_xh [(size_t)M_TOT * D];
__device__ __align__(16) __nv_bfloat16  g_xl [(size_t)M_TOT * D];
__device__ __align__(16) __nv_bfloat16  g_w1h[(size_t)DH * D];
__device__ __align__(16) __nv_bfloat16  g_w1l[(size_t)DH * D];
__device__ __align__(16) __nv_bfloat16  g_w2h[(size_t)D * DH];
__device__ __align__(16) __nv_bfloat16  g_w2l[(size_t)D * DH];
__device__ __align__(16) __nv_bfloat16  g_a2h[(size_t)M_TOT * DH];
__device__ __align__(16) __nv_bfloat16  g_a2l[(size_t)M_TOT * DH];
__device__ __align__(16) float2         g_Z[B * NC * DH];
__device__ __align__(16) float2         g_T[B * NC * DH];

// ---------------------------------------------------------------- PTX helpers
__device__ __forceinline__ uint32_t smem_u32(const void* p) {
    uint32_t a;
    asm("{ .reg .u64 t; cvta.to.shared.u64 t, %1; cvt.u32.u64 %0, t; }" : "=r"(a) : "l"(p));
    return a;
}
__device__ __forceinline__ void cp16(uint32_t s, const void* g) {
    asm volatile("cp.async.cg.shared.global [%0], [%1], 16;" :: "r"(s), "l"(g));
}
#define CP_COMMIT() asm volatile("cp.async.commit_group;" ::: "memory")
#define CP_WAIT1()  asm volatile("cp.async.wait_group 1;" ::: "memory")

__device__ __forceinline__ void ldsm4(uint32_t* r, uint32_t addr) {
    asm volatile("ldmatrix.sync.aligned.m8n8.x4.shared.b16 {%0,%1,%2,%3}, [%4];"
                 : "=r"(r[0]), "=r"(r[1]), "=r"(r[2]), "=r"(r[3]) : "r"(addr));
}
__device__ __forceinline__ void mma16816(float* d, const uint32_t* a, const uint32_t* b) {
    asm volatile(
        "mma.sync.aligned.m16n8k16.row.col.f32.bf16.bf16.f32 "
        "{%0,%1,%2,%3}, {%4,%5,%6,%7}, {%8,%9}, {%0,%1,%2,%3};"
        : "+f"(d[0]), "+f"(d[1]), "+f"(d[2]), "+f"(d[3])
        : "r"(a[0]), "r"(a[1]), "r"(a[2]), "r"(a[3]), "r"(b[0]), "r"(b[1]));
}

// XOR swizzle for a [128 rows][16 bf16] sub-tile (32 B/row, two 16B chunks/row).
__device__ __forceinline__ uint32_t swz(uint32_t row, uint32_t c) {
    return row * 32 + ((c ^ ((row >> 2) & 1)) << 4);
}

// ---------------------------------------------------------------- GEMM
// C[M,N] = A[M,K]*B[N,K]^T + bias[N], fp32 via bf16 hi/lo 3-term split
// (AhBh + AhBl + AlBh) on mma.sync. CTA tile 128x128, 8 warps (4x2),
// warp tile 32x64. BK=32 per pipeline slice (two BK=16 sub-tiles in the
// verified 32B-row swizzle layout). 3-stage cp.async, ONE barrier per slice.
// MODE 0: A=g_xh/g_xl,   B=g_w1h/g_w1l, C=g_h     (N=DH, K=D)
// MODE 1: A=g_a2h/g_a2l, B=g_w2h/g_w2l, C=Cparam  (N=D,  K=DH)
constexpr int TILE4  = 4096;           // one BK=16 sub-tile: 128 rows * 32 B
constexpr int STG    = 8 * TILE4;      // {Ah,Al,Bh,Bl} x {k0,k1} = 32 KB
constexpr int NSTAGE = 3;              // 96 KB dynamic smem
constexpr int SMEM_DYN = NSTAGE * STG;

template <int MODE>
__global__ __launch_bounds__(256, 2)
void gemm_mma_bf16x3(const float* __restrict__ bias, float* __restrict__ Cparam)
{
    constexpr int N = MODE ? D  : DH;
    constexpr int K = MODE ? DH : D;

    const __nv_bfloat16* __restrict__ Ah = MODE ? g_a2h : g_xh;
    const __nv_bfloat16* __restrict__ Al = MODE ? g_a2l : g_xl;
    const __nv_bfloat16* __restrict__ Bh = MODE ? g_w2h : g_w1h;
    const __nv_bfloat16* __restrict__ Bl = MODE ? g_w2l : g_w1l;
    float* __restrict__ C = MODE ? Cparam : g_h;

    extern __shared__ __align__(128) uint8_t smem[];
    const uint32_t sb = smem_u32(smem);

    const int tid  = threadIdx.x;
    const int wid  = tid >> 5;
    const int lane = tid & 31;
    const int wm   = (wid >> 1) * 32;          // warp row offset in CTA tile
    const int wn   = (wid & 1) * 64;           // warp col offset
    const int bm   = blockIdx.y * 128;
    const int bn   = blockIdx.x * 128;

    // loader mapping: thread -> (row = tid/2, 16B chunk = tid&1) per sub-tile
    const int lrow = tid >> 1;
    const int lc   = tid & 1;
    const uint32_t sw_st = swz(lrow, lc);
    const __nv_bfloat16* gAh = Ah + (size_t)(bm + lrow) * K + lc * 8;
    const __nv_bfloat16* gAl = Al + (size_t)(bm + lrow) * K + lc * 8;
    const __nv_bfloat16* gBh = Bh + (size_t)(bn + lrow) * K + lc * 8;
    const __nv_bfloat16* gBl = Bl + (size_t)(bn + lrow) * K + lc * 8;

    // ldmatrix source addresses (within-sub-tile byte offsets)
    const uint32_t swA = swz(wm + (lane & 15), lane >> 4);
    const uint32_t swB = swz(wn + ((lane >> 4) << 3) + (lane & 7), (lane >> 3) & 1);

    float acc[2][8][4];
#pragma unroll
    for (int mt = 0; mt < 2; mt++)
#pragma unroll
        for (int nt = 0; nt < 8; nt++)
#pragma unroll
            for (int r = 0; r < 4; r++) acc[mt][nt][r] = 0.f;

    constexpr int NIT = K / 32;                 // BK=32 slices

    // stage layout: sub-tile index = operand*2 + kk  (operand: 0=Ah,1=Al,2=Bh,3=Bl)
    auto load_stage = [&](int i, int st) {
        uint32_t base = sb + st * STG;
        int k0 = i * 32;
#pragma unroll
        for (int kk = 0; kk < 2; kk++) {
            int ko = k0 + kk * 16;
            cp16(base + (0 * 2 + kk) * TILE4 + sw_st, gAh + ko);
            cp16(base + (1 * 2 + kk) * TILE4 + sw_st, gAl + ko);
            cp16(base + (2 * 2 + kk) * TILE4 + sw_st, gBh + ko);
            cp16(base + (3 * 2 + kk) * TILE4 + sw_st, gBl + ko);
        }
        CP_COMMIT();
    };

    load_stage(0, 0);
    load_stage(1, 1);

    for (int i = 0; i < NIT; i++) {
        const int st = i % NSTAGE;
        const uint32_t base = sb + st * STG;
        CP_WAIT1();              // stage i landed (newest 1 group may be in flight)
        __syncthreads();         // single barrier per BK=32 slice

        // issue next stage's loads immediately — they fly during the mma chain
        if (i + 2 < NIT) load_stage(i + 2, (i + 2) % NSTAGE);
        else             CP_COMMIT();      // empty group keeps wait accounting exact

#pragma unroll
        for (int kk = 0; kk < 2; kk++) {
            const uint32_t bA = base + kk * TILE4;
            uint32_t a_h[2][4], a_l[2][4];
#pragma unroll
            for (int mt = 0; mt < 2; mt++) {
                ldsm4(a_h[mt], bA +             swA + mt * 512);
                ldsm4(a_l[mt], bA + 2 * TILE4 + swA + mt * 512);
            }
#pragma unroll
            for (int pr = 0; pr < 4; pr++) {
                uint32_t b_h[4], b_l[4];
                ldsm4(b_h, bA + 4 * TILE4 + swB + pr * 512);
                ldsm4(b_l, bA + 6 * TILE4 + swB + pr * 512);
#pragma unroll
                for (int mt = 0; mt < 2; mt++)
#pragma unroll
                    for (int s = 0; s < 2; s++) {
                        float* d = acc[mt][pr * 2 + s];
                        mma16816(d, a_h[mt], &b_h[s * 2]);
                        mma16816(d, a_h[mt], &b_l[s * 2]);
                        mma16816(d, a_l[mt], &b_h[s * 2]);
                    }
            }
        }
    }

    // epilogue: acc + bias -> C
#pragma unroll
    for (int mt = 0; mt < 2; mt++)
#pragma unroll
        for (int nt = 0; nt < 8; nt++) {
            const float* d = acc[mt][nt];
            int row = bm + wm + mt * 16 + (lane >> 2);
            int col = bn + wn + nt * 8 + (lane & 3) * 2;
            float b0 = bias[col], b1 = bias[col + 1];
            float2 v0 = {d[0] + b0, d[1] + b1};
            float2 v1 = {d[2] + b0, d[3] + b1};
            *reinterpret_cast<float2*>(C + (size_t)row * N + col)       = v0;
            *reinterpret_cast<float2*>(C + (size_t)(row + 8) * N + col) = v1;
        }
}

// ---------------------------------------------------------------- fp32 -> bf16 hi/lo split
// WHICH 0: x -> g_xh/g_xl;  1: W_in -> g_w1h/g_w1l;  2: W_out -> g_w2h/g_w2l
template <int WHICH>
__global__ void split_f32(const float* __restrict__ s)
{
    __nv_bfloat16* hi = (WHICH == 0) ? g_xh : (WHICH == 1) ? g_w1h : g_w2h;
    __nv_bfloat16* lo = (WHICH == 0) ? g_xl : (WHICH == 1) ? g_w1l : g_w2l;
    int i = (blockIdx.x * blockDim.x + threadIdx.x) * 4;
    float4 v = *reinterpret_cast<const float4*>(s + i);
    __nv_bfloat16 h0 = __float2bfloat16(v.x), h1 = __float2bfloat16(v.y);
    __nv_bfloat16 h2 = __float2bfloat16(v.z), h3 = __float2bfloat16(v.w);
    __nv_bfloat162 hp0{h0, h1}, hp1{h2, h3};
    __nv_bfloat162 lp0{__float2bfloat16(v.x - __bfloat162float(h0)),
                       __float2bfloat16(v.y - __bfloat162float(h1))};
    __nv_bfloat162 lp1{__float2bfloat16(v.z - __bfloat162float(h2)),
                       __float2bfloat16(v.w - __bfloat162float(h3))};
    *reinterpret_cast<__nv_bfloat162*>(hi + i)     = hp0;
    *reinterpret_cast<__nv_bfloat162*>(hi + i + 2) = hp1;
    *reinterpret_cast<__nv_bfloat162*>(lo + i)     = lp0;
    *reinterpret_cast<__nv_bfloat162*>(lo + i + 2) = lp1;
}

// ---------------------------------------------------------------- scan
__device__ __forceinline__ void load_pole(const float* phz, int c, float& Pr, float& Pi)
{
    float pr = phz[2 * c], pi = phz[2 * c + 1];
    float pa = sqrtf(pr * pr + pi * pi);
    float s  = expf(-pa) / pa;
    Pr = pr * s; Pi = pi * s;
}

__global__ void scan_chunks(const float* __restrict__ phz, const float* __restrict__ phz0)
{
    int idx = blockIdx.x * blockDim.x + threadIdx.x;   // (b*NC+j)*DH + c
    int c  = idx % DH;
    int bj = idx / DH;
    int j  = bj % NC;
    int b  = bj / NC;

    float Pr, Pi; load_pole(phz, c, Pr, Pi);
    float p0r = phz0[2 * c], p0i = phz0[2 * c + 1];

    const float* hp = g_h + ((size_t)b * L + (size_t)j * CL) * DH + c;
    float zr = 0.f, zi = 0.f;
#pragma unroll 8
    for (int i = 0; i < CL; i++) {
        float hv = hp[(size_t)i * DH];
        float nr = fmaf(Pr, zr, fmaf(-Pi, zi, p0r * hv));
        float ni = fmaf(Pr, zi, fmaf( Pi, zr, p0i * hv));
        zr = nr; zi = ni;
    }
    g_Z[idx] = make_float2(zr, zi);
}

__global__ void combine_chunks(const float* __restrict__ phz,
                               const float* __restrict__ last_re,
                               const float* __restrict__ last_im)
{
    int idx = blockIdx.x * blockDim.x + threadIdx.x;   // b*DH + c
    int c = idx % DH;
    int b = idx / DH;

    float Pr, Pi; load_pole(phz, c, Pr, Pi);

    // A = p^CL, CL = 64 = 2^6 (repeated squaring in double)
    double ar = (double)Pr, ai = (double)Pi;
#pragma unroll
    for (int s = 0; s < 6; s++) {
        double nr = ar * ar - ai * ai;
        double ni = 2.0 * ar * ai;
        ar = nr; ai = ni;
    }
    float Ar = (float)ar, Ai = (float)ai;

    float Tr = last_re[idx], Ti = last_im[idx];
#pragma unroll
    for (int j = 0; j < NC; j++) {
        int zi_idx = (b * NC + j) * DH + c;
        g_T[zi_idx] = make_float2(Tr, Ti);
        float2 z = g_Z[zi_idx];
        float nr = fmaf(Ar, Tr, fmaf(-Ai, Ti, z.x));
        float ni = fmaf(Ar, Ti, fmaf( Ai, Tr, z.y));
        Tr = nr; Ti = ni;
    }
}

// replay chunk; write silu result directly as bf16 hi/lo (GEMM2's A operand)
__global__ void apply_chunks(const float* __restrict__ phz, const float* __restrict__ phz0)
{
    int idx = blockIdx.x * blockDim.x + threadIdx.x;
    int c  = idx % DH;
    int bj = idx / DH;
    int j  = bj % NC;
    int b  = bj / NC;

    float Pr, Pi; load_pole(phz, c, Pr, Pi);
    float p0r = phz0[2 * c], p0i = phz0[2 * c + 1];

    float2 t0 = g_T[idx];
    float Tr = t0.x, Ti = t0.y;

    size_t base = ((size_t)b * L + (size_t)j * CL) * DH + c;
    const float* hp = g_h + base;
    __nv_bfloat16* ah = g_a2h + base;
    __nv_bfloat16* al = g_a2l + base;
#pragma unroll 8
    for (int i = 0; i < CL; i++) {
        float hv = hp[(size_t)i * DH];
        float nr = fmaf(Pr, Tr, fmaf(-Pi, Ti, p0r * hv));
        float ni = fmaf(Pr, Ti, fmaf( Pi, Tr, p0i * hv));
        Tr = nr; Ti = ni;
        float a = nr / (1.f + expf(-nr));          // SiLU
        __nv_bfloat16 h = __float2bfloat16(a);
        ah[(size_t)i * DH] = h;
        al[(size_t)i * DH] = __float2bfloat16(a - __bfloat162float(h));
    }
}

// ----------------------------------------------------------------
extern "C" void kernel_launch(void* const* d_in, const int* in_sizes, int n_in,
                              void* d_out, int out_size)
{
    const float* x     = (const float*)d_in[0];
    const float* W_in  = (const float*)d_in[1];
    const float* b_in  = (const float*)d_in[2];
    const float* W_out = (const float*)d_in[3];
    const float* b_out = (const float*)d_in[4];
    const float* phz   = (const float*)d_in[5];
    const float* phz0  = (const float*)d_in[6];
    const float* lre   = (const float*)d_in[7];
    const float* lim   = (const float*)d_in[8];
    float* out = (float*)d_out;

    // opt-in to 96 KB dynamic smem (idempotent, non-stream host API)
    cudaFuncSetAttribute(gemm_mma_bf16x3<0>,
                         cudaFuncAttributeMaxDynamicSharedMemorySize, SMEM_DYN);
    cudaFuncSetAttribute(gemm_mma_bf16x3<1>,
                         cudaFuncAttributeMaxDynamicSharedMemorySize, SMEM_DYN);

    // split fp32 inputs into bf16 hi/lo pairs (destinations bound in device code)
    split_f32<0><<<(M_TOT * D) / 1024, 256>>>(x);
    split_f32<1><<<(DH * D)    / 1024, 256>>>(W_in);
    split_f32<2><<<(D * DH)    / 1024, 256>>>(W_out);

    // GEMM1: h = x @ W_in^T + b_in   [8192 x 2048, K=1024] -> g_h
    gemm_mma_bf16x3<0><<<dim3(DH / 128, M_TOT / 128), 256, SMEM_DYN>>>(b_in, nullptr);

    // exact chunked complex scan + SiLU (emits bf16 hi/lo for GEMM2)
    scan_chunks<<<(B * NC * DH) / 256, 256>>>(phz, phz0);
    combine_chunks<<<(B * DH) / 256, 256>>>(phz, lre, lim);
    apply_chunks<<<(B * NC * DH) / 256, 256>>>(phz, phz0);

    // GEMM2: out = silu(conv) @ W_out^T + b_out   [8192 x 1024, K=2048]
    gemm_mma_bf16x3<1><<<dim3(D / 128, M_TOT / 128), 256, SMEM_DYN>>>(b_out, out);
}

// round 16
// speedup vs baseline: 1.0022x; 1.0022x over previous
#include <cuda_runtime.h>
#include <cuda_bf16.h>
#include <math.h>
#include <cstdint>

// ---------------------------------------------------------------- dims
constexpr int B  = 4;
constexpr int L  = 2048;
constexpr int D  = 1024;
constexpr int DH = 2048;
constexpr int M_TOT = B * L;            // 8192

// scan chunking
constexpr int NC = 32;
constexpr int CL = L / NC;              // 64

// persistent GEMM grid
constexpr int NSM   = 148;
constexpr int CTAS  = 2 * NSM;          // 2 CTAs resident per SM

// ---------------------------------------------------------------- scratch
// Referenced ONLY from device code (host-side symbol addresses are invalid).
__device__ __align__(16) float          g_h  [(size_t)M_TOT * DH];
__device__ __align__(16) __nv_bfloat16  g_xh [(size_t)M_TOT * D];
__device__ __align__(16) __nv_bfloat16  g_xl [(size_t)M_TOT * D];
__device__ __align__(16) __nv_bfloat16  g_w1h[(size_t)DH * D];
__device__ __align__(16) __nv_bfloat16  g_w1l[(size_t)DH * D];
__device__ __align__(16) __nv_bfloat16  g_w2h[(size_t)D * DH];
__device__ __align__(16) __nv_bfloat16  g_w2l[(size_t)D * DH];
__device__ __align__(16) __nv_bfloat16  g_a2h[(size_t)M_TOT * DH];
__device__ __align__(16) __nv_bfloat16  g_a2l[(size_t)M_TOT * DH];
__device__ __align__(16) float2         g_Z[B * NC * DH];
__device__ __align__(16) float2         g_T[B * NC * DH];

// ---------------------------------------------------------------- PTX helpers
__device__ __forceinline__ uint32_t smem_u32(const void* p) {
    uint32_t a;
    asm("{ .reg .u64 t; cvta.to.shared.u64 t, %1; cvt.u32.u64 %0, t; }" : "=r"(a) : "l"(p));
    return a;
}
__device__ __forceinline__ void cp16(uint32_t s, const void* g) {
    asm volatile("cp.async.cg.shared.global [%0], [%1], 16;" :: "r"(s), "l"(g));
}
#define CP_COMMIT() asm volatile("cp.async.commit_group;" ::: "memory")
#define CP_WAIT1()  asm volatile("cp.async.wait_group 1;" ::: "memory")

__device__ __forceinline__ void ldsm4(uint32_t* r, uint32_t addr) {
    asm volatile("ldmatrix.sync.aligned.m8n8.x4.shared.b16 {%0,%1,%2,%3}, [%4];"
                 : "=r"(r[0]), "=r"(r[1]), "=r"(r[2]), "=r"(r[3]) : "r"(addr));
}
__device__ __forceinline__ void mma16816(float* d, const uint32_t* a, const uint32_t* b) {
    asm volatile(
        "mma.sync.aligned.m16n8k16.row.col.f32.bf16.bf16.f32 "
        "{%0,%1,%2,%3}, {%4,%5,%6,%7}, {%8,%9}, {%0,%1,%2,%3};"
        : "+f"(d[0]), "+f"(d[1]), "+f"(d[2]), "+f"(d[3])
        : "r"(a[0]), "r"(a[1]), "r"(a[2]), "r"(a[3]), "r"(b[0]), "r"(b[1]));
}

// XOR swizzle for a [128 rows][16 bf16] tile (32 B/row, two 16B chunks/row).
__device__ __forceinline__ uint32_t swz(uint32_t row, uint32_t c) {
    return row * 32 + ((c ^ ((row >> 2) & 1)) << 4);
}

// ---------------------------------------------------------------- GEMM
// C[M,N] = A[M,K]*B[N,K]^T + bias[N], fp32 via bf16 hi/lo 3-term split
// (AhBh + AhBl + AlBh) on mma.sync. CTA tile 128x128, BK=16, 8 warps (4x2),
// warp tile 32x64, 3-stage cp.async, one barrier per slice.
// PERSISTENT: grid = 296 CTAs, each loops over output tiles (kills wave tail).
// MODE 0: A=g_xh/g_xl,   B=g_w1h/g_w1l, C=g_h     (N=DH, K=D)
// MODE 1: A=g_a2h/g_a2l, B=g_w2h/g_w2l, C=Cparam  (N=D,  K=DH)
constexpr int TILE4  = 4096;           // one operand tile: 128 rows * 32 B
constexpr int STG    = 4 * TILE4;      // Ah,Al,Bh,Bl per stage = 16 KB
constexpr int NSTAGE = 3;              // 48 KB static smem

template <int MODE>
__global__ __launch_bounds__(256, 2)
void gemm_mma_bf16x3(const float* __restrict__ bias, float* __restrict__ Cparam)
{
    constexpr int N = MODE ? D  : DH;
    constexpr int K = MODE ? DH : D;
    constexpr int NTILE_N = N / 128;
    constexpr int NTILES  = (M_TOT / 128) * NTILE_N;

    const __nv_bfloat16* __restrict__ Ah = MODE ? g_a2h : g_xh;
    const __nv_bfloat16* __restrict__ Al = MODE ? g_a2l : g_xl;
    const __nv_bfloat16* __restrict__ Bh = MODE ? g_w2h : g_w1h;
    const __nv_bfloat16* __restrict__ Bl = MODE ? g_w2l : g_w1l;
    float* __restrict__ C = MODE ? Cparam : g_h;

    __shared__ __align__(128) uint8_t smem[NSTAGE * STG];   // 48 KB
    const uint32_t sb = smem_u32(smem);

    const int tid  = threadIdx.x;
    const int wid  = tid >> 5;
    const int lane = tid & 31;
    const int wm   = (wid >> 1) * 32;          // warp row offset in CTA tile
    const int wn   = (wid & 1) * 64;           // warp col offset

    // loader mapping: thread -> (row = tid/2, 16B chunk = tid&1)
    const int lrow = tid >> 1;
    const int lc   = tid & 1;
    const uint32_t sw_st = swz(lrow, lc);

    // ldmatrix source addresses (within-stage byte offsets)
    const uint32_t swA = swz(wm + (lane & 15), lane >> 4);
    const uint32_t swB = swz(wn + ((lane >> 4) << 3) + (lane & 7), (lane >> 3) & 1);

    constexpr int NIT = K / 16;

    for (int t = blockIdx.x; t < NTILES; t += gridDim.x) {
        const int bm = (t / NTILE_N) * 128;
        const int bn = (t % NTILE_N) * 128;

        const __nv_bfloat16* gAh = Ah + (size_t)(bm + lrow) * K + lc * 8;
        const __nv_bfloat16* gAl = Al + (size_t)(bm + lrow) * K + lc * 8;
        const __nv_bfloat16* gBh = Bh + (size_t)(bn + lrow) * K + lc * 8;
        const __nv_bfloat16* gBl = Bl + (size_t)(bn + lrow) * K + lc * 8;

        float acc[2][8][4];
#pragma unroll
        for (int mt = 0; mt < 2; mt++)
#pragma unroll
            for (int nt = 0; nt < 8; nt++)
#pragma unroll
                for (int r = 0; r < 4; r++) acc[mt][nt][r] = 0.f;

        auto load_stage = [&](int i, int st) {
            uint32_t base = sb + st * STG;
            int k0 = i * 16;
            cp16(base +         0 + sw_st, gAh + k0);
            cp16(base +  TILE4    + sw_st, gAl + k0);
            cp16(base + 2 * TILE4 + sw_st, gBh + k0);
            cp16(base + 3 * TILE4 + sw_st, gBl + k0);
            CP_COMMIT();
        };

        load_stage(0, 0);
        load_stage(1, 1);

        for (int i = 0; i < NIT; i++) {
            const int st = i % NSTAGE;
            const uint32_t base = sb + st * STG;
            CP_WAIT1();              // stage i landed (newest group may be in flight)
            __syncthreads();         // single barrier per slice (reuse distance = 3)

            // issue next stage's loads — they fly during the mma chain
            if (i + 2 < NIT) load_stage(i + 2, (i + 2) % NSTAGE);
            else             CP_COMMIT();     // empty group keeps accounting exact

            uint32_t a_h[2][4], a_l[2][4];
#pragma unroll
            for (int mt = 0; mt < 2; mt++) {
                ldsm4(a_h[mt], base +             swA + mt * 512);
                ldsm4(a_l[mt], base + TILE4     + swA + mt * 512);
            }
#pragma unroll
            for (int pr = 0; pr < 4; pr++) {
                uint32_t b_h[4], b_l[4];
                ldsm4(b_h, base + 2 * TILE4 + swB + pr * 512);
                ldsm4(b_l, base + 3 * TILE4 + swB + pr * 512);
#pragma unroll
                for (int mt = 0; mt < 2; mt++)
#pragma unroll
                    for (int s = 0; s < 2; s++) {
                        float* d = acc[mt][pr * 2 + s];
                        mma16816(d, a_h[mt], &b_h[s * 2]);
                        mma16816(d, a_h[mt], &b_l[s * 2]);
                        mma16816(d, a_l[mt], &b_h[s * 2]);
                    }
            }
        }

        // all warps done reading this tile's smem before next tile overwrites it
        __syncthreads();

        // epilogue: acc + bias -> C (registers only, overlaps next tile's loads)
#pragma unroll
        for (int mt = 0; mt < 2; mt++)
#pragma unroll
            for (int nt = 0; nt < 8; nt++) {
                const float* d = acc[mt][nt];
                int row = bm + wm + mt * 16 + (lane >> 2);
                int col = bn + wn + nt * 8 + (lane & 3) * 2;
                float b0 = bias[col], b1 = bias[col + 1];
                float2 v0 = {d[0] + b0, d[1] + b1};
                float2 v1 = {d[2] + b0, d[3] + b1};
                *reinterpret_cast<float2*>(C + (size_t)row * N + col)       = v0;
                *reinterpret_cast<float2*>(C + (size_t)(row + 8) * N + col) = v1;
            }
    }
}

// ---------------------------------------------------------------- fp32 -> bf16 hi/lo split
// WHICH 0: x -> g_xh/g_xl;  1: W_in -> g_w1h/g_w1l;  2: W_out -> g_w2h/g_w2l
template <int WHICH>
__global__ void split_f32(const float* __restrict__ s)
{
    __nv_bfloat16* hi = (WHICH == 0) ? g_xh : (WHICH == 1) ? g_w1h : g_w2h;
    __nv_bfloat16* lo = (WHICH == 0) ? g_xl : (WHICH == 1) ? g_w1l : g_w2l;
    int i = (blockIdx.x * blockDim.x + threadIdx.x) * 4;
    float4 v = *reinterpret_cast<const float4*>(s + i);
    __nv_bfloat16 h0 = __float2bfloat16(v.x), h1 = __float2bfloat16(v.y);
    __nv_bfloat16 h2 = __float2bfloat16(v.z), h3 = __float2bfloat16(v.w);
    __nv_bfloat162 hp0{h0, h1}, hp1{h2, h3};
    __nv_bfloat162 lp0{__float2bfloat16(v.x - __bfloat162float(h0)),
                       __float2bfloat16(v.y - __bfloat162float(h1))};
    __nv_bfloat162 lp1{__float2bfloat16(v.z - __bfloat162float(h2)),
                       __float2bfloat16(v.w - __bfloat162float(h3))};
    *reinterpret_cast<__nv_bfloat162*>(hi + i)     = hp0;
    *reinterpret_cast<__nv_bfloat162*>(hi + i + 2) = hp1;
    *reinterpret_cast<__nv_bfloat162*>(lo + i)     = lp0;
    *reinterpret_cast<__nv_bfloat162*>(lo + i + 2) = lp1;
}

// ---------------------------------------------------------------- scan
__device__ __forceinline__ void load_pole(const float* phz, int c, float& Pr, float& Pi)
{
    float pr = phz[2 * c], pi = phz[2 * c + 1];
    float pa = sqrtf(pr * pr + pi * pi);
    float s  = expf(-pa) / pa;
    Pr = pr * s; Pi = pi * s;
}

__global__ void scan_chunks(const float* __restrict__ phz, const float* __restrict__ phz0)
{
    int idx = blockIdx.x * blockDim.x + threadIdx.x;   // (b*NC+j)*DH + c
    int c  = idx % DH;
    int bj = idx / DH;
    int j  = bj % NC;
    int b  = bj / NC;

    float Pr, Pi; load_pole(phz, c, Pr, Pi);
    float p0r = phz0[2 * c], p0i = phz0[2 * c + 1];

    const float* hp = g_h + ((size_t)b * L + (size_t)j * CL) * DH + c;
    float zr = 0.f, zi = 0.f;
#pragma unroll 8
    for (int i = 0; i < CL; i++) {
        float hv = hp[(size_t)i * DH];
        float nr = fmaf(Pr, zr, fmaf(-Pi, zi, p0r * hv));
        float ni = fmaf(Pr, zi, fmaf( Pi, zr, p0i * hv));
        zr = nr; zi = ni;
    }
    g_Z[idx] = make_float2(zr, zi);
}

__global__ void combine_chunks(const float* __restrict__ phz,
                               const float* __restrict__ last_re,
                               const float* __restrict__ last_im)
{
    int idx = blockIdx.x * blockDim.x + threadIdx.x;   // b*DH + c
    int c = idx % DH;
    int b = idx / DH;

    float Pr, Pi; load_pole(phz, c, Pr, Pi);

    // A = p^CL, CL = 64 = 2^6 (repeated squaring in double)
    double ar = (double)Pr, ai = (double)Pi;
#pragma unroll
    for (int s = 0; s < 6; s++) {
        double nr = ar * ar - ai * ai;
        double ni = 2.0 * ar * ai;
        ar = nr; ai = ni;
    }
    float Ar = (float)ar, Ai = (float)ai;

    float Tr = last_re[idx], Ti = last_im[idx];
#pragma unroll
    for (int j = 0; j < NC; j++) {
        int zi_idx = (b * NC + j) * DH + c;
        g_T[zi_idx] = make_float2(Tr, Ti);
        float2 z = g_Z[zi_idx];
        float nr = fmaf(Ar, Tr, fmaf(-Ai, Ti, z.x));
        float ni = fmaf(Ar, Ti, fmaf( Ai, Tr, z.y));
        Tr = nr; Ti = ni;
    }
}

// replay chunk; write silu result directly as bf16 hi/lo (GEMM2's A operand)
__global__ void apply_chunks(const float* __restrict__ phz, const float* __restrict__ phz0)
{
    int idx = blockIdx.x * blockDim.x + threadIdx.x;
    int c  = idx % DH;
    int bj = idx / DH;
    int j  = bj % NC;
    int b  = bj / NC;

    float Pr, Pi; load_pole(phz, c, Pr, Pi);
    float p0r = phz0[2 * c], p0i = phz0[2 * c + 1];

    float2 t0 = g_T[idx];
    float Tr = t0.x, Ti = t0.y;

    size_t base = ((size_t)b * L + (size_t)j * CL) * DH + c;
    const float* hp = g_h + base;
    __nv_bfloat16* ah = g_a2h + base;
    __nv_bfloat16* al = g_a2l + base;
#pragma unroll 8
    for (int i = 0; i < CL; i++) {
        float hv = hp[(size_t)i * DH];
        float nr = fmaf(Pr, Tr, fmaf(-Pi, Ti, p0r * hv));
        float ni = fmaf(Pr, Ti, fmaf( Pi, Tr, p0i * hv));
        Tr = nr; Ti = ni;
        float a = nr / (1.f + expf(-nr));          // SiLU
        __nv_bfloat16 h = __float2bfloat16(a);
        ah[(size_t)i * DH] = h;
        al[(size_t)i * DH] = __float2bfloat16(a - __bfloat162float(h));
    }
}

// ----------------------------------------------------------------
extern "C" void kernel_launch(void* const* d_in, const int* in_sizes, int n_in,
                              void* d_out, int out_size)
{
    const float* x     = (const float*)d_in[0];
    const float* W_in  = (const float*)d_in[1];
    const float* b_in  = (const float*)d_in[2];
    const float* W_out = (const float*)d_in[3];
    const float* b_out = (const float*)d_in[4];
    const float* phz   = (const float*)d_in[5];
    const float* phz0  = (const float*)d_in[6];
    const float* lre   = (const float*)d_in[7];
    const float* lim   = (const float*)d_in[8];
    float* out = (float*)d_out;

    // split fp32 inputs into bf16 hi/lo pairs (destinations bound in device code)
    split_f32<0><<<(M_TOT * D) / 1024, 256>>>(x);
    split_f32<1><<<(DH * D)    / 1024, 256>>>(W_in);
    split_f32<2><<<(D * DH)    / 1024, 256>>>(W_out);

    // GEMM1: h = x @ W_in^T + b_in   [8192 x 2048, K=1024] -> g_h  (persistent)
    gemm_mma_bf16x3<0><<<CTAS, 256>>>(b_in, nullptr);

    // exact chunked complex scan + SiLU (emits bf16 hi/lo for GEMM2)
    scan_chunks<<<(B * NC * DH) / 256, 256>>>(phz, phz0);
    combine_chunks<<<(B * DH) / 256, 256>>>(phz, lre, lim);
    apply_chunks<<<(B * NC * DH) / 256, 256>>>(phz, phz0);

    // GEMM2: out = silu(conv) @ W_out^T + b_out   [8192 x 1024, K=2048]  (persistent)
    gemm_mma_bf16x3<1><<<CTAS, 256>>>(b_out, out);
}

// round 17
// speedup vs baseline: 1.0142x; 1.0119x over previous
#include <cuda_runtime.h>
#include <cuda_bf16.h>
#include <math.h>
#include <cstdint>

// ---------------------------------------------------------------- dims
constexpr int B  = 4;
constexpr int L  = 2048;
constexpr int D  = 1024;
constexpr int DH = 2048;
constexpr int M_TOT = B * L;            // 8192

// scan chunking
constexpr int NC = 32;
constexpr int CL = L / NC;              // 64

// ---------------------------------------------------------------- scratch
// Referenced ONLY from device code (host-side symbol addresses are invalid).
__device__ __align__(16) float          g_h  [(size_t)M_TOT * DH];
__device__ __align__(16) __nv_bfloat16  g_xh [(size_t)M_TOT * D];
__device__ __align__(16) __nv_bfloat16  g_xl [(size_t)M_TOT * D];
__device__ __align__(16) __nv_bfloat16  g_w1h[(size_t)DH * D];
__device__ __align__(16) __nv_bfloat16  g_w1l[(size_t)DH * D];
__device__ __align__(16) __nv_bfloat16  g_w2h[(size_t)D * DH];
__device__ __align__(16) __nv_bfloat16  g_w2l[(size_t)D * DH];
__device__ __align__(16) __nv_bfloat16  g_a2h[(size_t)M_TOT * DH];
__device__ __align__(16) __nv_bfloat16  g_a2l[(size_t)M_TOT * DH];
__device__ __align__(16) float2         g_Z[B * NC * DH];
__device__ __align__(16) float2         g_T[B * NC * DH];

// ---------------------------------------------------------------- PTX helpers
__device__ __forceinline__ uint32_t smem_u32(const void* p) {
    uint32_t a;
    asm("{ .reg .u64 t; cvta.to.shared.u64 t, %1; cvt.u32.u64 %0, t; }" : "=r"(a) : "l"(p));
    return a;
}
__device__ __forceinline__ void cp16(uint32_t s, const void* g) {
    asm volatile("cp.async.cg.shared.global [%0], [%1], 16;" :: "r"(s), "l"(g));
}
#define CP_COMMIT() asm volatile("cp.async.commit_group;" ::: "memory")
#define CP_WAIT1()  asm volatile("cp.async.wait_group 1;" ::: "memory")

__device__ __forceinline__ void ldsm4(uint32_t* r, uint32_t addr) {
    asm volatile("ldmatrix.sync.aligned.m8n8.x4.shared.b16 {%0,%1,%2,%3}, [%4];"
                 : "=r"(r[0]), "=r"(r[1]), "=r"(r[2]), "=r"(r[3]) : "r"(addr));
}
__device__ __forceinline__ void mma16816(float* d, const uint32_t* a, const uint32_t* b) {
    asm volatile(
        "mma.sync.aligned.m16n8k16.row.col.f32.bf16.bf16.f32 "
        "{%0,%1,%2,%3}, {%4,%5,%6,%7}, {%8,%9}, {%0,%1,%2,%3};"
        : "+f"(d[0]), "+f"(d[1]), "+f"(d[2]), "+f"(d[3])
        : "r"(a[0]), "r"(a[1]), "r"(a[2]), "r"(a[3]), "r"(b[0]), "r"(b[1]));
}

// XOR swizzle for a [128 rows][16 bf16] tile (32 B/row, two 16B chunks/row).
__device__ __forceinline__ uint32_t swz(uint32_t row, uint32_t c) {
    return row * 32 + ((c ^ ((row >> 2) & 1)) << 4);
}

// ---------------------------------------------------------------- GEMM
// C[M,N] = A[M,K]*B[N,K]^T + bias[N], fp32 via bf16 hi/lo 3-term split
// (AhBh + AhBl + AlBh) on mma.sync. CTA tile 128x128, BK=16, 8 warps (4x2),
// warp tile 32x64, 3-stage cp.async, one barrier per slice.
// mma issue order is TERM-MAJOR within each pr group: same-accumulator
// dependency distance = 4 mmas instead of 1 (hides HMMA latency).
// MODE 0: A=g_xh/g_xl,   B=g_w1h/g_w1l, C=g_h     (N=DH, K=D)
// MODE 1: A=g_a2h/g_a2l, B=g_w2h/g_w2l, C=Cparam  (N=D,  K=DH)
constexpr int TILE4  = 4096;           // one operand tile: 128 rows * 32 B
constexpr int STG    = 4 * TILE4;      // Ah,Al,Bh,Bl per stage = 16 KB
constexpr int NSTAGE = 3;              // 48 KB static smem

template <int MODE>
__global__ __launch_bounds__(256, 2)
void gemm_mma_bf16x3(const float* __restrict__ bias, float* __restrict__ Cparam)
{
    constexpr int N = MODE ? D  : DH;
    constexpr int K = MODE ? DH : D;

    const __nv_bfloat16* __restrict__ Ah = MODE ? g_a2h : g_xh;
    const __nv_bfloat16* __restrict__ Al = MODE ? g_a2l : g_xl;
    const __nv_bfloat16* __restrict__ Bh = MODE ? g_w2h : g_w1h;
    const __nv_bfloat16* __restrict__ Bl = MODE ? g_w2l : g_w1l;
    float* __restrict__ C = MODE ? Cparam : g_h;

    __shared__ __align__(128) uint8_t smem[NSTAGE * STG];   // 48 KB
    const uint32_t sb = smem_u32(smem);

    const int tid  = threadIdx.x;
    const int wid  = tid >> 5;
    const int lane = tid & 31;
    const int wm   = (wid >> 1) * 32;          // warp row offset in CTA tile
    const int wn   = (wid & 1) * 64;           // warp col offset
    const int bm   = blockIdx.y * 128;
    const int bn   = blockIdx.x * 128;

    // loader mapping: thread -> (row = tid/2, 16B chunk = tid&1)
    const int lrow = tid >> 1;
    const int lc   = tid & 1;
    const uint32_t sw_st = swz(lrow, lc);
    const __nv_bfloat16* gAh = Ah + (size_t)(bm + lrow) * K + lc * 8;
    const __nv_bfloat16* gAl = Al + (size_t)(bm + lrow) * K + lc * 8;
    const __nv_bfloat16* gBh = Bh + (size_t)(bn + lrow) * K + lc * 8;
    const __nv_bfloat16* gBl = Bl + (size_t)(bn + lrow) * K + lc * 8;

    // ldmatrix source addresses (within-stage byte offsets)
    const uint32_t swA = swz(wm + (lane & 15), lane >> 4);
    const uint32_t swB = swz(wn + ((lane >> 4) << 3) + (lane & 7), (lane >> 3) & 1);

    float acc[2][8][4];
#pragma unroll
    for (int mt = 0; mt < 2; mt++)
#pragma unroll
        for (int nt = 0; nt < 8; nt++)
#pragma unroll
            for (int r = 0; r < 4; r++) acc[mt][nt][r] = 0.f;

    constexpr int NIT = K / 16;

    auto load_stage = [&](int i, int st) {
        uint32_t base = sb + st * STG;
        int k0 = i * 16;
        cp16(base +         0 + sw_st, gAh + k0);
        cp16(base +  TILE4    + sw_st, gAl + k0);
        cp16(base + 2 * TILE4 + sw_st, gBh + k0);
        cp16(base + 3 * TILE4 + sw_st, gBl + k0);
        CP_COMMIT();
    };

    load_stage(0, 0);
    load_stage(1, 1);

    for (int i = 0; i < NIT; i++) {
        const int st = i % NSTAGE;
        const uint32_t base = sb + st * STG;
        CP_WAIT1();              // stage i landed (newest 1 group may be in flight)
        __syncthreads();         // single barrier per slice (reuse distance = 3)

        // issue next stage's loads immediately — they fly during the mma chain
        if (i + 2 < NIT) load_stage(i + 2, (i + 2) % NSTAGE);
        else             CP_COMMIT();      // empty group keeps wait accounting exact

        uint32_t a_h[2][4], a_l[2][4];
#pragma unroll
        for (int mt = 0; mt < 2; mt++) {
            ldsm4(a_h[mt], base +             swA + mt * 512);
            ldsm4(a_l[mt], base + TILE4     + swA + mt * 512);
        }
#pragma unroll
        for (int pr = 0; pr < 4; pr++) {
            uint32_t b_h[4], b_l[4];
            ldsm4(b_h, base + 2 * TILE4 + swB + pr * 512);
            ldsm4(b_l, base + 3 * TILE4 + swB + pr * 512);
            // term-major: 4 independent mmas per term; same-acc distance = 4
#pragma unroll
            for (int mt = 0; mt < 2; mt++)
#pragma unroll
                for (int s = 0; s < 2; s++)
                    mma16816(acc[mt][pr * 2 + s], a_h[mt], &b_h[s * 2]);
#pragma unroll
            for (int mt = 0; mt < 2; mt++)
#pragma unroll
                for (int s = 0; s < 2; s++)
                    mma16816(acc[mt][pr * 2 + s], a_h[mt], &b_l[s * 2]);
#pragma unroll
            for (int mt = 0; mt < 2; mt++)
#pragma unroll
                for (int s = 0; s < 2; s++)
                    mma16816(acc[mt][pr * 2 + s], a_l[mt], &b_h[s * 2]);
        }
    }

    // epilogue: acc + bias -> C
#pragma unroll
    for (int mt = 0; mt < 2; mt++)
#pragma unroll
        for (int nt = 0; nt < 8; nt++) {
            const float* d = acc[mt][nt];
            int row = bm + wm + mt * 16 + (lane >> 2);
            int col = bn + wn + nt * 8 + (lane & 3) * 2;
            float b0 = bias[col], b1 = bias[col + 1];
            float2 v0 = {d[0] + b0, d[1] + b1};
            float2 v1 = {d[2] + b0, d[3] + b1};
            *reinterpret_cast<float2*>(C + (size_t)row * N + col)       = v0;
            *reinterpret_cast<float2*>(C + (size_t)(row + 8) * N + col) = v1;
        }
}

// ---------------------------------------------------------------- fp32 -> bf16 hi/lo split
// WHICH 0: x -> g_xh/g_xl;  1: W_in -> g_w1h/g_w1l;  2: W_out -> g_w2h/g_w2l
template <int WHICH>
__global__ void split_f32(const float* __restrict__ s)
{
    __nv_bfloat16* hi = (WHICH == 0) ? g_xh : (WHICH == 1) ? g_w1h : g_w2h;
    __nv_bfloat16* lo = (WHICH == 0) ? g_xl : (WHICH == 1) ? g_w1l : g_w2l;
    int i = (blockIdx.x * blockDim.x + threadIdx.x) * 4;
    float4 v = *reinterpret_cast<const float4*>(s + i);
    __nv_bfloat16 h0 = __float2bfloat16(v.x), h1 = __float2bfloat16(v.y);
    __nv_bfloat16 h2 = __float2bfloat16(v.z), h3 = __float2bfloat16(v.w);
    __nv_bfloat162 hp0{h0, h1}, hp1{h2, h3};
    __nv_bfloat162 lp0{__float2bfloat16(v.x - __bfloat162float(h0)),
                       __float2bfloat16(v.y - __bfloat162float(h1))};
    __nv_bfloat162 lp1{__float2bfloat16(v.z - __bfloat162float(h2)),
                       __float2bfloat16(v.w - __bfloat162float(h3))};
    *reinterpret_cast<__nv_bfloat162*>(hi + i)     = hp0;
    *reinterpret_cast<__nv_bfloat162*>(hi + i + 2) = hp1;
    *reinterpret_cast<__nv_bfloat162*>(lo + i)     = lp0;
    *reinterpret_cast<__nv_bfloat162*>(lo + i + 2) = lp1;
}

// ---------------------------------------------------------------- scan
__device__ __forceinline__ void load_pole(const float* phz, int c, float& Pr, float& Pi)
{
    float pr = phz[2 * c], pi = phz[2 * c + 1];
    float pa = sqrtf(pr * pr + pi * pi);
    float s  = expf(-pa) / pa;
    Pr = pr * s; Pi = pi * s;
}

__global__ void scan_chunks(const float* __restrict__ phz, const float* __restrict__ phz0)
{
    int idx = blockIdx.x * blockDim.x + threadIdx.x;   // (b*NC+j)*DH + c
    int c  = idx % DH;
    int bj = idx / DH;
    int j  = bj % NC;
    int b  = bj / NC;

    float Pr, Pi; load_pole(phz, c, Pr, Pi);
    float p0r = phz0[2 * c], p0i = phz0[2 * c + 1];

    const float* hp = g_h + ((size_t)b * L + (size_t)j * CL) * DH + c;
    float zr = 0.f, zi = 0.f;
#pragma unroll 8
    for (int i = 0; i < CL; i++) {
        float hv = hp[(size_t)i * DH];
        float nr = fmaf(Pr, zr, fmaf(-Pi, zi, p0r * hv));
        float ni = fmaf(Pr, zi, fmaf( Pi, zr, p0i * hv));
        zr = nr; zi = ni;
    }
    g_Z[idx] = make_float2(zr, zi);
}

__global__ void combine_chunks(const float* __restrict__ phz,
                               const float* __restrict__ last_re,
                               const float* __restrict__ last_im)
{
    int idx = blockIdx.x * blockDim.x + threadIdx.x;   // b*DH + c
    int c = idx % DH;
    int b = idx / DH;

    float Pr, Pi; load_pole(phz, c, Pr, Pi);

    // A = p^CL, CL = 64 = 2^6 (repeated squaring in double)
    double ar = (double)Pr, ai = (double)Pi;
#pragma unroll
    for (int s = 0; s < 6; s++) {
        double nr = ar * ar - ai * ai;
        double ni = 2.0 * ar * ai;
        ar = nr; ai = ni;
    }
    float Ar = (float)ar, Ai = (float)ai;

    float Tr = last_re[idx], Ti = last_im[idx];
#pragma unroll
    for (int j = 0; j < NC; j++) {
        int zi_idx = (b * NC + j) * DH + c;
        g_T[zi_idx] = make_float2(Tr, Ti);
        float2 z = g_Z[zi_idx];
        float nr = fmaf(Ar, Tr, fmaf(-Ai, Ti, z.x));
        float ni = fmaf(Ar, Ti, fmaf( Ai, Tr, z.y));
        Tr = nr; Ti = ni;
    }
}

// replay chunk; write silu result directly as bf16 hi/lo (GEMM2's A operand)
__global__ void apply_chunks(const float* __restrict__ phz, const float* __restrict__ phz0)
{
    int idx = blockIdx.x * blockDim.x + threadIdx.x;
    int c  = idx % DH;
    int bj = idx / DH;
    int j  = bj % NC;
    int b  = bj / NC;

    float Pr, Pi; load_pole(phz, c, Pr, Pi);
    float p0r = phz0[2 * c], p0i = phz0[2 * c + 1];

    float2 t0 = g_T[idx];
    float Tr = t0.x, Ti = t0.y;

    size_t base = ((size_t)b * L + (size_t)j * CL) * DH + c;
    const float* hp = g_h + base;
    __nv_bfloat16* ah = g_a2h + base;
    __nv_bfloat16* al = g_a2l + base;
#pragma unroll 8
    for (int i = 0; i < CL; i++) {
        float hv = hp[(size_t)i * DH];
        float nr = fmaf(Pr, Tr, fmaf(-Pi, Ti, p0r * hv));
        float ni = fmaf(Pr, Ti, fmaf( Pi, Tr, p0i * hv));
        Tr = nr; Ti = ni;
        float a = nr / (1.f + expf(-nr));          // SiLU
        __nv_bfloat16 h = __float2bfloat16(a);
        ah[(size_t)i * DH] = h;
        al[(size_t)i * DH] = __float2bfloat16(a - __bfloat162float(h));
    }
}

// ----------------------------------------------------------------
extern "C" void kernel_launch(void* const* d_in, const int* in_sizes, int n_in,
                              void* d_out, int out_size)
{
    const float* x     = (const float*)d_in[0];
    const float* W_in  = (const float*)d_in[1];
    const float* b_in  = (const float*)d_in[2];
    const float* W_out = (const float*)d_in[3];
    const float* b_out = (const float*)d_in[4];
    const float* phz   = (const float*)d_in[5];
    const float* phz0  = (const float*)d_in[6];
    const float* lre   = (const float*)d_in[7];
    const float* lim   = (const float*)d_in[8];
    float* out = (float*)d_out;

    // split fp32 inputs into bf16 hi/lo pairs (destinations bound in device code)
    split_f32<0><<<(M_TOT * D) / 1024, 256>>>(x);
    split_f32<1><<<(DH * D)    / 1024, 256>>>(W_in);
    split_f32<2><<<(D * DH)    / 1024, 256>>>(W_out);

    // GEMM1: h = x @ W_in^T + b_in   [8192 x 2048, K=1024] -> g_h
    gemm_mma_bf16x3<0><<<dim3(DH / 128, M_TOT / 128), 256>>>(b_in, nullptr);

    // exact chunked complex scan + SiLU (emits bf16 hi/lo for GEMM2)
    scan_chunks<<<(B * NC * DH) / 256, 256>>>(phz, phz0);
    combine_chunks<<<(B * DH) / 256, 256>>>(phz, lre, lim);
    apply_chunks<<<(B * NC * DH) / 256, 256>>>(phz, phz0);

    // GEMM2: out = silu(conv) @ W_out^T + b_out   [8192 x 1024, K=2048]
    gemm_mma_bf16x3<1><<<dim3(D / 128, M_TOT / 128), 256>>>(b_out, out);
}